// round 2
// baseline (speedup 1.0000x reference)
#include <cuda_runtime.h>

#define NN 2048
#define NE 32768
#define DF 2048
#define TOPK 20
#define RMAXF 1e-5f
#define RPB 16
#define PSTR 20               // pushv row stride in floats (float4-aligned)
#define SRC_CAP 8192
#define SC_T 128
#define NTHREADS 1024
#define NBLOCKS (NN / RPB)    // 128
#define MAX_ITERS 200

// ---------------- device scratch ----------------
__device__ __align__(16) float g_P[(size_t)NN * NN];  // transposed: P^T[k][i]
__device__ __align__(16) float g_R[(size_t)NN * NN];  // transposed: R^T[k][i]
__device__ float g_halfinv[NN];
__device__ int g_deg[NN], g_indeg[NN];
__device__ int g_rowptr[NN + 1], g_colptr[NN + 1];
__device__ int g_fillr[NN], g_fillc[NN];
__device__ int g_dst[NE];  // CSR out-edges (per-row sorted)
__device__ int g_src[NE];  // CSC in-edges  (per-col sorted)

// ---------------- graph build ----------------
__global__ void k_zero() {
    int t = threadIdx.x;
    for (int k = t; k < NN; k += blockDim.x) {
        g_deg[k] = 0; g_indeg[k] = 0; g_fillr[k] = 0; g_fillc[k] = 0;
    }
}

__global__ void k_count(const int* __restrict__ ei) {
    int e = blockIdx.x * blockDim.x + threadIdx.x;
    if (e >= NE) return;
    atomicAdd(&g_deg[ei[e]], 1);
    atomicAdd(&g_indeg[ei[NE + e]], 1);
}

__global__ void k_scan() {
    __shared__ int s[256];
    int t = threadIdx.x;
    for (int pass = 0; pass < 2; pass++) {
        const int* cnt = pass ? g_deg : g_indeg;
        int* ptr = pass ? g_rowptr : g_colptr;
        int base = t * 8;
        int v[8]; int sum = 0;
#pragma unroll
        for (int m = 0; m < 8; m++) { v[m] = cnt[base + m]; sum += v[m]; }
        s[t] = sum; __syncthreads();
        for (int off = 1; off < 256; off <<= 1) {
            int x = (t >= off) ? s[t - off] : 0;
            __syncthreads();
            s[t] += x;
            __syncthreads();
        }
        int excl = (t == 0) ? 0 : s[t - 1];
#pragma unroll
        for (int m = 0; m < 8; m++) { ptr[base + m] = excl; excl += v[m]; }
        if (t == 255) ptr[NN] = excl;
        __syncthreads();
    }
    int base = t * 8;
#pragma unroll
    for (int m = 0; m < 8; m++) {
        int d = g_deg[base + m];
        g_halfinv[base + m] = 0.5f / (d ? (float)d : 1.f);
    }
}

__global__ void k_fill(const int* __restrict__ ei) {
    int e = blockIdx.x * blockDim.x + threadIdx.x;
    if (e >= NE) return;
    int r = ei[e], c = ei[NE + e];
    int pr = atomicAdd(&g_fillr[r], 1);
    g_dst[g_rowptr[r] + pr] = c;
    int pc = atomicAdd(&g_fillc[c], 1);
    g_src[g_colptr[c] + pc] = r;
}

__device__ __forceinline__ void insort(int* a, int n) {
    for (int i = 1; i < n; i++) {
        int x = a[i]; int j = i - 1;
        while (j >= 0 && a[j] > x) { a[j + 1] = a[j]; j--; }
        a[j + 1] = x;
    }
}

__global__ void k_sort() {
    int id = blockIdx.x * blockDim.x + threadIdx.x;
    if (id >= 2 * NN) return;
    int* arr; int p0, p1;
    if (id < NN) { arr = g_src; p0 = g_colptr[id]; p1 = g_colptr[id + 1]; }
    else { arr = g_dst; p0 = g_rowptr[id - NN]; p1 = g_rowptr[id - NN + 1]; }
    int n = p1 - p0;
    if (n <= 1) return;
    if (n <= 160) {
        int buf[160];
        for (int i = 0; i < n; i++) buf[i] = arr[p0 + i];
        insort(buf, n);
        for (int i = 0; i < n; i++) arr[p0 + i] = buf[i];
    } else {
        insort(arr + p0, n);
    }
}

// ---------------- persistent push + fused topk/output ----------------
__global__ void __launch_bounds__(NTHREADS, 1)
k_push(const float* __restrict__ X, float* __restrict__ out) {
    extern __shared__ float sh[];
    float* pv = sh;                          // [NN * PSTR] masked push * (0.5/deg)
    int* ssrc = (int*)(sh + NN * PSTR);      // [SRC_CAP] staged CSC chunk
    __shared__ int s_cnt, s_cnt2;
    __shared__ int s_list[SC_T];
    __shared__ float s_redv[32];
    __shared__ int s_redi[32];
    __shared__ float s_tv[RPB][TOPK];
    __shared__ int s_ti[RPB][TOPK];

    const int tid = threadIdx.x;
    const int row0 = blockIdx.x * RPB;
    const int g = tid >> 4;    // 64 groups for phase-1 / init (group = k lane)
    const int r = tid & 15;    // row within tile
    const int q = tid >> 2;    // 256 quads for gather (quad = column j)
    const int rq = tid & 3;    // 4 rows per lane (float4)

    // init own slice of R^T (identity) and P^T (zero) — tile columns are block-private
    for (int m = 0; m < 32; m++) {
        int k = g + 64 * m;
        size_t o = (size_t)k * NN + row0 + r;
        g_P[o] = 0.f;
        g_R[o] = (k == row0 + r) ? 1.f : 0.f;
    }
    __syncthreads();

    for (int iter = 0; iter < MAX_ITERS; iter++) {
        if (tid == 0) { s_cnt = 0; s_cnt2 = 0; }
        __syncthreads();

        // ---- phase 1: snapshot masked push values, accumulate P, count pushes
        int localcnt = 0;
        for (int m = 0; m < 32; m++) {
            int k = g + 64 * m;
            size_t o = (size_t)k * NN + row0 + r;
            float val = g_R[o];
            bool push = (val >= RMAXF);
            pv[k * PSTR + r] = push ? val * g_halfinv[k] : 0.f;
            if (push) { g_P[o] += 0.5f * val; localcnt++; }
        }
        localcnt = __reduce_add_sync(0xffffffffu, localcnt);
        if ((tid & 31) == 0 && localcnt) atomicAdd(&s_cnt, localcnt);
        __syncthreads();
        int cnt = s_cnt;
        if (cnt == 0) break;  // tile fully converged, R untouched

        bool any = false;
        if (cnt <= SC_T) {
            // ---- sparse scatter path (in-place)
            for (int m = 0; m < 32; m++) {
                int k = g + 64 * m;
                if (pv[k * PSTR + r] > 0.f) {
                    int pos = atomicAdd(&s_cnt2, 1);
                    s_list[pos] = (k << 4) | r;
                }
            }
            __syncthreads();
            for (int l = tid; l < cnt; l += NTHREADS) {
                int k2 = s_list[l] >> 4, r2 = s_list[l] & 15;
                g_R[(size_t)k2 * NN + row0 + r2] = 0.f;  // pushed entry: keep = 0
            }
            __syncthreads();
            for (int l = tid; l < cnt; l += NTHREADS) {
                int k2 = s_list[l] >> 4, r2 = s_list[l] & 15;
                float w = pv[k2 * PSTR + r2];
                int p0 = g_rowptr[k2], p1 = g_rowptr[k2 + 1];
                for (int p = p0; p < p1; p++)
                    atomicAdd(&g_R[(size_t)g_dst[p] * NN + row0 + r2], w);
            }
            __syncthreads();
            for (int l = tid; l < cnt; l += NTHREADS) {
                int k2 = s_list[l] >> 4, r2 = s_list[l] & 15;
                any |= (g_R[(size_t)k2 * NN + row0 + r2] >= RMAXF);
                int p0 = g_rowptr[k2], p1 = g_rowptr[k2 + 1];
                for (int p = p0; p < p1; p++)
                    any |= (g_R[(size_t)g_dst[p] * NN + row0 + r2] >= RMAXF);
            }
        } else {
            // ---- dense gather path (CSC), chunked index staging, float4 over rows
            for (int c = 0; c < NN / 256; c++) {
                int jbase = c * 256;
                int ebase = g_colptr[jbase], eend = g_colptr[jbase + 256];
                for (int e = ebase + tid; e < eend; e += NTHREADS)
                    if (e - ebase < SRC_CAP) ssrc[e - ebase] = g_src[e];
                __syncthreads();

                int j = jbase + q;  // one column per quad per chunk
                int p0 = g_colptr[j], p1 = g_colptr[j + 1];
                float4 acc = make_float4(0.f, 0.f, 0.f, 0.f);
                for (int p = p0; p < p1; p++) {
                    int s = (p - ebase < SRC_CAP) ? ssrc[p - ebase] : g_src[p];
                    const float4 v = *(const float4*)&pv[s * PSTR + rq * 4];
                    acc.x += v.x; acc.y += v.y; acc.z += v.z; acc.w += v.w;
                }
                size_t o = (size_t)j * NN + row0 + rq * 4;
                float4 kp = *(const float4*)&g_R[o];
                kp.x = (kp.x >= RMAXF) ? 0.f : kp.x;
                kp.y = (kp.y >= RMAXF) ? 0.f : kp.y;
                kp.z = (kp.z >= RMAXF) ? 0.f : kp.z;
                kp.w = (kp.w >= RMAXF) ? 0.f : kp.w;
                float4 nv = make_float4(kp.x + acc.x, kp.y + acc.y,
                                        kp.z + acc.z, kp.w + acc.w);
                any |= (nv.x >= RMAXF) | (nv.y >= RMAXF) |
                       (nv.z >= RMAXF) | (nv.w >= RMAXF);
                *(float4*)&g_R[o] = nv;
                __syncthreads();  // protect ssrc before next chunk
            }
        }
        if (!__syncthreads_or(any ? 1 : 0)) break;
    }

    // ---------------- fused top-k + output for this tile ----------------
    __syncthreads();
    for (int m = 0; m < 32; m++) {
        int k = g + 64 * m;
        pv[k * PSTR + r] = g_P[(size_t)k * NN + row0 + r];
    }
    __syncthreads();

    const int rg = tid >> 6;   // row group (16 rows)
    const int tl = tid & 63;   // 64 threads per row
    const int wid = tid >> 5, lane = tid & 31;

    for (int t = 0; t < TOPK; t++) {
        float bv = -1.f; int bi = NN;
        for (int m = 0; m < 32; m++) {
            int j = tl + 64 * m;
            float v = pv[j * PSTR + rg];
            if (v > bv || (v == bv && j < bi)) { bv = v; bi = j; }
        }
        for (int off = 16; off; off >>= 1) {
            float ov = __shfl_down_sync(0xffffffffu, bv, off);
            int oi = __shfl_down_sync(0xffffffffu, bi, off);
            if (ov > bv || (ov == bv && oi < bi)) { bv = ov; bi = oi; }
        }
        if (lane == 0) { s_redv[wid] = bv; s_redi[wid] = bi; }
        __syncthreads();
        if (tl == 0) {
            float v0 = s_redv[2 * rg], v1 = s_redv[2 * rg + 1];
            int i0 = s_redi[2 * rg], i1 = s_redi[2 * rg + 1];
            if (v1 > v0 || (v1 == v0 && i1 < i0)) { v0 = v1; i0 = i1; }
            s_tv[rg][t] = v0; s_ti[rg][t] = i0;
            pv[i0 * PSTR + rg] = -2.f;  // remove from further selection
        }
        __syncthreads();
    }

    float tv[TOPK]; int ti[TOPK];
#pragma unroll
    for (int t = 0; t < TOPK; t++) { tv[t] = s_tv[rg][t]; ti[t] = s_ti[rg][t]; }
    for (int m = 0; m < 32; m++) {
        int cidx = tl + 64 * m;
        float acc = 0.f;
#pragma unroll
        for (int t = 0; t < TOPK; t++)
            acc += tv[t] * X[(size_t)ti[t] * DF + cidx];
        out[(size_t)(row0 + rg) * DF + cidx] = acc;
    }
}

// ---------------- launch ----------------
extern "C" void kernel_launch(void* const* d_in, const int* in_sizes, int n_in,
                              void* d_out, int out_size) {
    const float* X;
    const int* ei;
    if (in_sizes[0] == 2 * NE) { ei = (const int*)d_in[0]; X = (const float*)d_in[1]; }
    else { X = (const float*)d_in[0]; ei = (const int*)d_in[1]; }
    float* out = (float*)d_out;

    const int smem = NN * PSTR * sizeof(float) + SRC_CAP * sizeof(int);  // 196608
    cudaFuncSetAttribute(k_push, cudaFuncAttributeMaxDynamicSharedMemorySize, smem);

    k_zero<<<1, 1024>>>();
    k_count<<<NE / 256, 256>>>(ei);
    k_scan<<<1, 256>>>();
    k_fill<<<NE / 256, 256>>>(ei);
    k_sort<<<(2 * NN) / 256, 256>>>();
    k_push<<<NBLOCKS, NTHREADS, smem>>>(X, out);
}

// round 3
// speedup vs baseline: 1.3422x; 1.3422x over previous
#include <cuda_runtime.h>

#define NN 2048
#define NE 32768
#define DF 2048
#define TOPK 20
#define RMAXF 1e-5f
#define ROWS 4
#define NTILES (NN / ROWS)      // 512
#define NTHREADS 256
#define GRID 296
#define LISTCAP 512
#define MAXIT 500

// ---------------- device scratch ----------------
__device__ int g_deg[NN], g_indeg[NN];
__device__ int g_rowptr[NN + 1], g_colptr[NN + 1];
__device__ int g_fillr[NN], g_fillc[NN];
__device__ float g_halfinv[NN];
__device__ int g_dst[NE];   // CSR out-edges (per-row sorted)
__device__ int g_src[NE];   // CSC in-edges  (per-col sorted)
__device__ int g_work;

// ---------------- graph build ----------------
__global__ void k_zero() {
    int t = threadIdx.x;
    for (int k = t; k < NN; k += blockDim.x) {
        g_deg[k] = 0; g_indeg[k] = 0; g_fillr[k] = 0; g_fillc[k] = 0;
    }
    if (t == 0) g_work = 0;
}

__global__ void k_count(const int* __restrict__ ei) {
    int e = blockIdx.x * blockDim.x + threadIdx.x;
    if (e >= NE) return;
    atomicAdd(&g_deg[ei[e]], 1);
    atomicAdd(&g_indeg[ei[NE + e]], 1);
}

__global__ void k_scan() {
    __shared__ int s[256];
    int t = threadIdx.x;
    for (int pass = 0; pass < 2; pass++) {
        const int* cnt = pass ? g_deg : g_indeg;
        int* ptr = pass ? g_rowptr : g_colptr;
        int base = t * 8;
        int v[8]; int sum = 0;
#pragma unroll
        for (int m = 0; m < 8; m++) { v[m] = cnt[base + m]; sum += v[m]; }
        s[t] = sum; __syncthreads();
        for (int off = 1; off < 256; off <<= 1) {
            int x = (t >= off) ? s[t - off] : 0;
            __syncthreads();
            s[t] += x;
            __syncthreads();
        }
        int excl = (t == 0) ? 0 : s[t - 1];
#pragma unroll
        for (int m = 0; m < 8; m++) { ptr[base + m] = excl; excl += v[m]; }
        if (t == 255) ptr[NN] = excl;
        __syncthreads();
    }
    int base = t * 8;
#pragma unroll
    for (int m = 0; m < 8; m++) {
        int d = g_deg[base + m];
        g_halfinv[base + m] = 0.5f / (d ? (float)d : 1.f);
    }
}

__global__ void k_fill(const int* __restrict__ ei) {
    int e = blockIdx.x * blockDim.x + threadIdx.x;
    if (e >= NE) return;
    int r = ei[e], c = ei[NE + e];
    int pr = atomicAdd(&g_fillr[r], 1);
    g_dst[g_rowptr[r] + pr] = c;
    int pc = atomicAdd(&g_fillc[c], 1);
    g_src[g_colptr[c] + pc] = r;
}

__device__ __forceinline__ void insort(int* a, int n) {
    for (int i = 1; i < n; i++) {
        int x = a[i]; int j = i - 1;
        while (j >= 0 && a[j] > x) { a[j + 1] = a[j]; j--; }
        a[j + 1] = x;
    }
}

// canonicalize adjacency-list order -> deterministic summation order
__global__ void k_sort() {
    int id = blockIdx.x * blockDim.x + threadIdx.x;
    if (id >= 2 * NN) return;
    int* arr; int p0, p1;
    if (id < NN) { arr = g_src; p0 = g_colptr[id]; p1 = g_colptr[id + 1]; }
    else { arr = g_dst; p0 = g_rowptr[id - NN]; p1 = g_rowptr[id - NN + 1]; }
    int n = p1 - p0;
    if (n <= 1) return;
    if (n <= 160) {
        int buf[160];
        for (int i = 0; i < n; i++) buf[i] = arr[p0 + i];
        insort(buf, n);
        for (int i = 0; i < n; i++) arr[p0 + i] = buf[i];
    } else {
        insort(arr + p0, n);
    }
}

// ---------------- persistent all-in-shared push + fused topk/output ----------------
__global__ void __launch_bounds__(NTHREADS, 2)
k_push(const float* __restrict__ X, float* __restrict__ out) {
    extern __shared__ float sh[];
    float* Ra = sh;                     // [ROWS*NN] residual buffer A
    float* Rb = Ra + ROWS * NN;         // [ROWS*NN] residual buffer B
    float* Pp = Rb + ROWS * NN;         // [ROWS*NN] P accumulator
    float* shh = Pp + ROWS * NN;        // [NN] 0.5/deg
    float* lw = shh + NN;               // [LISTCAP] push values
    int* lk = (int*)(lw + LISTCAP);     // [LISTCAP] packed entry index
    __shared__ int s_cnt, s_cnt2, s_tile;
    __shared__ float s_redv[8];
    __shared__ int s_redi[8];
    __shared__ float s_tv[ROWS][TOPK];
    __shared__ int s_ti[ROWS][TOPK];

    const int tid = threadIdx.x;
    const int lane = tid & 31;

    for (int k = tid; k < NN; k += NTHREADS) shh[k] = g_halfinv[k];

    while (true) {
        if (tid == 0) s_tile = atomicAdd(&g_work, 1);
        __syncthreads();
        const int t = s_tile;
        if (t >= NTILES) break;
        const int row0 = t * ROWS;

        // ---- init tile state in shared (no global R/P at all)
        for (int e = tid; e < ROWS * NN; e += NTHREADS) {
            int k = e >> 2, r = e & 3;
            Ra[e] = (k == row0 + r) ? 1.f : 0.f;
            Pp[e] = 0.f;
        }
        float* cur = Ra;
        float* nxt = Rb;
        __syncthreads();

        for (int iter = 0; iter < MAXIT; iter++) {
            if (tid == 0) { s_cnt = 0; s_cnt2 = 0; }
            __syncthreads();
            // ---- count pushes (warp-aggregated)
            int c = 0;
#pragma unroll
            for (int m = 0; m < ROWS * NN / NTHREADS; m++)
                c += (cur[tid + NTHREADS * m] >= RMAXF);
            c = __reduce_add_sync(0xffffffffu, c);
            if (lane == 0 && c) atomicAdd(&s_cnt, c);
            __syncthreads();
            const int cnt = s_cnt;
            if (cnt == 0) break;

            bool any = false;
            if (cnt <= LISTCAP) {
                // ---- sparse frontier path (in-place, shared atomics)
#pragma unroll
                for (int m = 0; m < ROWS * NN / NTHREADS; m++) {
                    int e = tid + NTHREADS * m;
                    float v = cur[e];
                    bool pr = (v >= RMAXF);
                    unsigned msk = __ballot_sync(0xffffffffu, pr);
                    int base = 0;
                    if (lane == 0 && msk) base = atomicAdd(&s_cnt2, __popc(msk));
                    base = __shfl_sync(0xffffffffu, base, 0);
                    if (pr) {
                        int pos = base + __popc(msk & ((1u << lane) - 1));
                        lk[pos] = e; lw[pos] = v;
                    }
                }
                __syncthreads();
                for (int l = tid; l < cnt; l += NTHREADS) {
                    int e = lk[l];
                    cur[e] = 0.f;
                    Pp[e] += 0.5f * lw[l];
                }
                __syncthreads();
                for (int l = tid; l < cnt; l += NTHREADS) {
                    int e = lk[l], k = e >> 2, r = e & 3;
                    float w = lw[l] * shh[k];
                    int p1 = g_rowptr[k + 1];
                    for (int p = g_rowptr[k]; p < p1; p++)
                        atomicAdd(&cur[(g_dst[p] << 2) | r], w);
                }
                __syncthreads();
                for (int l = tid; l < cnt; l += NTHREADS) {
                    int e = lk[l], k = e >> 2, r = e & 3;
                    any |= (cur[e] >= RMAXF);
                    int p1 = g_rowptr[k + 1];
                    for (int p = g_rowptr[k]; p < p1; p++)
                        any |= (cur[(g_dst[p] << 2) | r] >= RMAXF);
                }
            } else {
                // ---- dense path: CSC gather with inline masking, float4 over rows
                float4* cur4 = (float4*)cur;
                float4* nxt4 = (float4*)nxt;
                float4* P4 = (float4*)Pp;
#pragma unroll
                for (int m = 0; m < NN / NTHREADS; m++) {
                    int j = tid + NTHREADS * m;
                    float4 cv = cur4[j];
                    float4 pv = P4[j];
                    float4 acc;
                    if (cv.x >= RMAXF) { pv.x += 0.5f * cv.x; acc.x = 0.f; } else acc.x = cv.x;
                    if (cv.y >= RMAXF) { pv.y += 0.5f * cv.y; acc.y = 0.f; } else acc.y = cv.y;
                    if (cv.z >= RMAXF) { pv.z += 0.5f * cv.z; acc.z = 0.f; } else acc.z = cv.z;
                    if (cv.w >= RMAXF) { pv.w += 0.5f * cv.w; acc.w = 0.f; } else acc.w = cv.w;
                    P4[j] = pv;
                    int p1 = g_colptr[j + 1];
                    for (int p = g_colptr[j]; p < p1; p++) {
                        int s = __ldg(&g_src[p]);
                        float h = shh[s];
                        float4 v = cur4[s];
                        if (v.x >= RMAXF) acc.x += v.x * h;
                        if (v.y >= RMAXF) acc.y += v.y * h;
                        if (v.z >= RMAXF) acc.z += v.z * h;
                        if (v.w >= RMAXF) acc.w += v.w * h;
                    }
                    nxt4[j] = acc;
                    any |= (acc.x >= RMAXF) | (acc.y >= RMAXF) |
                           (acc.z >= RMAXF) | (acc.w >= RMAXF);
                }
                float* tmp = cur; cur = nxt; nxt = tmp;
            }
            if (!__syncthreads_or(any ? 1 : 0)) break;
        }
        __syncthreads();

        // ---- fused top-k per row (64 threads per row)
        const int rg = tid >> 6;
        const int tl = tid & 63;
        const int wid = tid >> 5;
        for (int q = 0; q < TOPK; q++) {
            float bv = -1.f; int bi = NN;
#pragma unroll
            for (int m = 0; m < NN / 64; m++) {
                int j = tl + 64 * m;
                float v = Pp[(j << 2) | rg];
                if (v > bv || (v == bv && j < bi)) { bv = v; bi = j; }
            }
#pragma unroll
            for (int off = 16; off; off >>= 1) {
                float ov = __shfl_down_sync(0xffffffffu, bv, off);
                int oi = __shfl_down_sync(0xffffffffu, bi, off);
                if (ov > bv || (ov == bv && oi < bi)) { bv = ov; bi = oi; }
            }
            if (lane == 0) { s_redv[wid] = bv; s_redi[wid] = bi; }
            __syncthreads();
            if (tl == 0) {
                float v0 = s_redv[2 * rg], v1 = s_redv[2 * rg + 1];
                int i0 = s_redi[2 * rg], i1 = s_redi[2 * rg + 1];
                if (v1 > v0 || (v1 == v0 && i1 < i0)) { v0 = v1; i0 = i1; }
                s_tv[rg][q] = v0; s_ti[rg][q] = i0;
                Pp[(i0 << 2) | rg] = -2.f;
            }
            __syncthreads();
        }

        // ---- output GEMV: out[row0+rg, :] = sum_q tv[q] * X[ti[q], :]
#pragma unroll
        for (int m = 0; m < NN / 64; m++) {
            int col = tl + 64 * m;
            float acc = 0.f;
#pragma unroll
            for (int q = 0; q < TOPK; q++)
                acc += s_tv[rg][q] * __ldg(&X[(size_t)s_ti[rg][q] * DF + col]);
            out[(size_t)(row0 + rg) * DF + col] = acc;
        }
        // next-tile barrier is the s_tile __syncthreads at loop top
    }
}

// ---------------- launch ----------------
extern "C" void kernel_launch(void* const* d_in, const int* in_sizes, int n_in,
                              void* d_out, int out_size) {
    const float* X;
    const int* ei;
    if (in_sizes[0] == 2 * NE) { ei = (const int*)d_in[0]; X = (const float*)d_in[1]; }
    else { X = (const float*)d_in[0]; ei = (const int*)d_in[1]; }
    float* out = (float*)d_out;

    const int smem = (3 * ROWS * NN + NN + LISTCAP) * sizeof(float)
                   + LISTCAP * sizeof(int);   // 110592 B
    cudaFuncSetAttribute(k_push, cudaFuncAttributeMaxDynamicSharedMemorySize, smem);

    k_zero<<<1, 1024>>>();
    k_count<<<NE / 256, 256>>>(ei);
    k_scan<<<1, 256>>>();
    k_fill<<<NE / 256, 256>>>(ei);
    k_sort<<<(2 * NN) / 256, 256>>>();
    k_push<<<GRID, NTHREADS, smem>>>(X, out);
}

// round 4
// speedup vs baseline: 1.4150x; 1.0542x over previous
#include <cuda_runtime.h>

#define NN 2048
#define NE 32768
#define DF 2048
#define TOPK 20
#define RMAXF 1e-5f
#define ROWS 4
#define NTILES (NN / ROWS)      // 512
#define NTHREADS 512
#define GRID 148
#define LISTCAP 512
#define MAXIT 500

// ---------------- device scratch ----------------
__device__ int g_deg[NN], g_indeg[NN];
__device__ int g_rowptr[NN + 1], g_colptr[NN + 1];
__device__ int g_fillr[NN], g_fillc[NN];
__device__ float g_halfinv[NN];
__device__ int g_dst[NE];   // CSR out-edges (per-row sorted)
__device__ int g_src[NE];   // CSC in-edges  (per-col sorted)
__device__ int g_work;

// ---------------- graph build ----------------
__global__ void k_zero() {
    int t = threadIdx.x;
    for (int k = t; k < NN; k += blockDim.x) {
        g_deg[k] = 0; g_indeg[k] = 0; g_fillr[k] = 0; g_fillc[k] = 0;
    }
    if (t == 0) g_work = 0;
}

__global__ void k_count(const int* __restrict__ ei) {
    int e = blockIdx.x * blockDim.x + threadIdx.x;
    if (e >= NE) return;
    atomicAdd(&g_deg[ei[e]], 1);
    atomicAdd(&g_indeg[ei[NE + e]], 1);
}

__global__ void k_scan() {
    __shared__ int s[256];
    int t = threadIdx.x;
    for (int pass = 0; pass < 2; pass++) {
        const int* cnt = pass ? g_deg : g_indeg;
        int* ptr = pass ? g_rowptr : g_colptr;
        int base = t * 8;
        int v[8]; int sum = 0;
#pragma unroll
        for (int m = 0; m < 8; m++) { v[m] = cnt[base + m]; sum += v[m]; }
        s[t] = sum; __syncthreads();
        for (int off = 1; off < 256; off <<= 1) {
            int x = (t >= off) ? s[t - off] : 0;
            __syncthreads();
            s[t] += x;
            __syncthreads();
        }
        int excl = (t == 0) ? 0 : s[t - 1];
#pragma unroll
        for (int m = 0; m < 8; m++) { ptr[base + m] = excl; excl += v[m]; }
        if (t == 255) ptr[NN] = excl;
        __syncthreads();
    }
    int base = t * 8;
#pragma unroll
    for (int m = 0; m < 8; m++) {
        int d = g_deg[base + m];
        g_halfinv[base + m] = 0.5f / (d ? (float)d : 1.f);
    }
}

__global__ void k_fill(const int* __restrict__ ei) {
    int e = blockIdx.x * blockDim.x + threadIdx.x;
    if (e >= NE) return;
    int r = ei[e], c = ei[NE + e];
    int pr = atomicAdd(&g_fillr[r], 1);
    g_dst[g_rowptr[r] + pr] = c;
    int pc = atomicAdd(&g_fillc[c], 1);
    g_src[g_colptr[c] + pc] = r;
}

__device__ __forceinline__ void insort(int* a, int n) {
    for (int i = 1; i < n; i++) {
        int x = a[i]; int j = i - 1;
        while (j >= 0 && a[j] > x) { a[j + 1] = a[j]; j--; }
        a[j + 1] = x;
    }
}

__global__ void k_sort() {
    int id = blockIdx.x * blockDim.x + threadIdx.x;
    if (id >= 2 * NN) return;
    int* arr; int p0, p1;
    if (id < NN) { arr = g_src; p0 = g_colptr[id]; p1 = g_colptr[id + 1]; }
    else { arr = g_dst; p0 = g_rowptr[id - NN]; p1 = g_rowptr[id - NN + 1]; }
    int n = p1 - p0;
    if (n <= 1) return;
    if (n <= 160) {
        int buf[160];
        for (int i = 0; i < n; i++) buf[i] = arr[p0 + i];
        insort(buf, n);
        for (int i = 0; i < n; i++) arr[p0 + i] = buf[i];
    } else {
        insort(arr + p0, n);
    }
}

// ---------------- persistent all-in-shared push + fused topk/output ----------------
__global__ void __launch_bounds__(NTHREADS, 1)
k_push(const float* __restrict__ X, float* __restrict__ out) {
    extern __shared__ float sh[];
    float* pv = sh;                               // [ROWS*NN] masked push*(0.5/deg)
    float* cur = pv + ROWS * NN;                  // [ROWS*NN] residual (in-place)
    float* Pp = cur + ROWS * NN;                  // [ROWS*NN] P accumulator
    float* shh = Pp + ROWS * NN;                  // [NN] 0.5/deg
    int* scol = (int*)(shh + NN);                 // [NN+1] CSC colptr
    unsigned short* ssrc = (unsigned short*)(scol + NN + 4);  // [NE] CSC src (u16)
    int* lk = (int*)(ssrc + NE);                  // [LISTCAP]
    __shared__ int s_cnt, s_cnt2, s_tile;
    __shared__ float s_redv[16];
    __shared__ int s_redi[16];
    __shared__ float s_tv[ROWS][TOPK];
    __shared__ int s_ti[ROWS][TOPK];

    float4* pv4 = (float4*)pv;
    float4* cur4 = (float4*)cur;
    float4* Pp4 = (float4*)Pp;

    const int tid = threadIdx.x;
    const int lane = tid & 31;
    const int wid = tid >> 5;

    // ---- stage tile-invariant graph data once per CTA
    for (int k = tid; k < NN; k += NTHREADS) shh[k] = g_halfinv[k];
    for (int k = tid; k <= NN; k += NTHREADS) scol[k] = g_colptr[k];
    for (int e = tid; e < NE; e += NTHREADS) ssrc[e] = (unsigned short)g_src[e];

    while (true) {
        __syncthreads();
        if (tid == 0) s_tile = atomicAdd(&g_work, 1);
        __syncthreads();
        const int t = s_tile;
        if (t >= NTILES) break;
        const int row0 = t * ROWS;

        // ---- init tile state in shared
#pragma unroll
        for (int m = 0; m < NN / NTHREADS; m++) {
            int j = tid + NTHREADS * m;  // column k
            float4 z = make_float4(0.f, 0.f, 0.f, 0.f);
            Pp4[j] = z;
            int d = j - row0;
            if (d >= 0 && d < ROWS) ((float*)&z)[d] = 1.f;
            cur4[j] = z;
        }
        __syncthreads();

        for (int iter = 0; iter < MAXIT; iter++) {
            if (tid == 0) { s_cnt = 0; s_cnt2 = 0; }
            __syncthreads();

            // ---- phase A: mask, snapshot pv, keep in cur, accumulate P, count
            int c = 0;
#pragma unroll
            for (int m = 0; m < NN / NTHREADS; m++) {
                int j = tid + NTHREADS * m;
                float4 v = cur4[j];
                float h = shh[j];
                bool px = v.x >= RMAXF, py = v.y >= RMAXF,
                     pz = v.z >= RMAXF, pw = v.w >= RMAXF;
                float4 pvv = make_float4(px ? v.x * h : 0.f, py ? v.y * h : 0.f,
                                         pz ? v.z * h : 0.f, pw ? v.w * h : 0.f);
                pv4[j] = pvv;
                if (px | py | pz | pw) {
                    float4 p = Pp4[j];
                    if (px) { p.x += 0.5f * v.x; v.x = 0.f; c++; }
                    if (py) { p.y += 0.5f * v.y; v.y = 0.f; c++; }
                    if (pz) { p.z += 0.5f * v.z; v.z = 0.f; c++; }
                    if (pw) { p.w += 0.5f * v.w; v.w = 0.f; c++; }
                    Pp4[j] = p;
                    cur4[j] = v;
                }
            }
            c = __reduce_add_sync(0xffffffffu, c);
            if (lane == 0 && c) atomicAdd(&s_cnt, c);
            __syncthreads();
            const int cnt = s_cnt;
            if (cnt == 0) break;

            bool any = false;
            if (cnt <= LISTCAP) {
                // ---- sparse path: build frontier from pv, scatter via CSR
#pragma unroll
                for (int m = 0; m < NN / NTHREADS; m++) {
                    int j = tid + NTHREADS * m;
                    float4 v = pv4[j];
#pragma unroll
                    for (int r = 0; r < 4; r++) {
                        bool pr = ((float*)&v)[r] > 0.f;
                        unsigned msk = __ballot_sync(0xffffffffu, pr);
                        int base = 0;
                        if (lane == 0 && msk) base = atomicAdd(&s_cnt2, __popc(msk));
                        base = __shfl_sync(0xffffffffu, base, 0);
                        if (pr) lk[base + __popc(msk & ((1u << lane) - 1))] = (j << 2) | r;
                    }
                }
                __syncthreads();
                for (int l = tid; l < cnt; l += NTHREADS) {
                    int e = lk[l], k = e >> 2, r = e & 3;
                    float w = pv[e];
                    int p1 = g_rowptr[k + 1];
                    for (int p = g_rowptr[k]; p < p1; p++)
                        atomicAdd(&cur[(g_dst[p] << 2) | r], w);
                }
                __syncthreads();
                for (int l = tid; l < cnt; l += NTHREADS) {
                    int e = lk[l], k = e >> 2, r = e & 3;
                    any |= (cur[e] >= RMAXF);
                    int p1 = g_rowptr[k + 1];
                    for (int p = g_rowptr[k]; p < p1; p++)
                        any |= (cur[(g_dst[p] << 2) | r] >= RMAXF);
                }
            } else {
                // ---- dense path: pure-LDS CSC gather, float4 across rows
#pragma unroll
                for (int m = 0; m < NN / NTHREADS; m++) {
                    int j = tid + NTHREADS * m;
                    int p0 = scol[j], p1 = scol[j + 1];
                    float4 acc = cur4[j];  // keep
#pragma unroll 4
                    for (int p = p0; p < p1; p++) {
                        float4 v = pv4[ssrc[p]];
                        acc.x += v.x; acc.y += v.y; acc.z += v.z; acc.w += v.w;
                    }
                    cur4[j] = acc;
                    any |= (acc.x >= RMAXF) | (acc.y >= RMAXF) |
                           (acc.z >= RMAXF) | (acc.w >= RMAXF);
                }
            }
            if (!__syncthreads_or(any ? 1 : 0)) break;
        }
        __syncthreads();

        // ---- fused top-k per row (128 threads per row)
        const int rg = tid >> 7;
        const int tl = tid & 127;
        for (int q = 0; q < TOPK; q++) {
            float bv = -1.f; int bi = NN;
#pragma unroll
            for (int m = 0; m < NN / 128; m++) {
                int j = tl + 128 * m;
                float v = Pp[(j << 2) | rg];
                if (v > bv || (v == bv && j < bi)) { bv = v; bi = j; }
            }
#pragma unroll
            for (int off = 16; off; off >>= 1) {
                float ov = __shfl_down_sync(0xffffffffu, bv, off);
                int oi = __shfl_down_sync(0xffffffffu, bi, off);
                if (ov > bv || (ov == bv && oi < bi)) { bv = ov; bi = oi; }
            }
            if (lane == 0) { s_redv[wid] = bv; s_redi[wid] = bi; }
            __syncthreads();
            if (tl == 0) {
                float v0 = s_redv[4 * rg]; int i0 = s_redi[4 * rg];
#pragma unroll
                for (int w = 1; w < 4; w++) {
                    float v1 = s_redv[4 * rg + w]; int i1 = s_redi[4 * rg + w];
                    if (v1 > v0 || (v1 == v0 && i1 < i0)) { v0 = v1; i0 = i1; }
                }
                s_tv[rg][q] = v0; s_ti[rg][q] = i0;
                Pp[(i0 << 2) | rg] = -2.f;
            }
            __syncthreads();
        }

        // ---- output GEMV: out[row0+rg, :] = sum_q tv[q] * X[ti[q], :]
        float tv[TOPK]; int ti[TOPK];
#pragma unroll
        for (int q = 0; q < TOPK; q++) {
            tv[q] = s_tv[rg][q];
            ti[q] = s_ti[rg][q] * (DF / 4);
        }
        const float4* X4 = (const float4*)X;
        float4* out4 = (float4*)out;
#pragma unroll
        for (int m = 0; m < DF / 4 / 128; m++) {
            int col = tl + 128 * m;
            float4 acc = make_float4(0.f, 0.f, 0.f, 0.f);
#pragma unroll
            for (int q = 0; q < TOPK; q++) {
                float w = tv[q];
                float4 x = __ldg(&X4[ti[q] + col]);
                acc.x += w * x.x; acc.y += w * x.y;
                acc.z += w * x.z; acc.w += w * x.w;
            }
            out4[(size_t)(row0 + rg) * (DF / 4) + col] = acc;
        }
    }
}

// ---------------- launch ----------------
extern "C" void kernel_launch(void* const* d_in, const int* in_sizes, int n_in,
                              void* d_out, int out_size) {
    const float* X;
    const int* ei;
    if (in_sizes[0] == 2 * NE) { ei = (const int*)d_in[0]; X = (const float*)d_in[1]; }
    else { X = (const float*)d_in[0]; ei = (const int*)d_in[1]; }
    float* out = (float*)d_out;

    const int smem = (3 * ROWS * NN + NN) * sizeof(float)
                   + (NN + 4) * sizeof(int)
                   + NE * sizeof(unsigned short)
                   + LISTCAP * sizeof(int);       // ~182 KB
    cudaFuncSetAttribute(k_push, cudaFuncAttributeMaxDynamicSharedMemorySize, smem);

    k_zero<<<1, 1024>>>();
    k_count<<<NE / 256, 256>>>(ei);
    k_scan<<<1, 256>>>();
    k_fill<<<NE / 256, 256>>>(ei);
    k_sort<<<(2 * NN) / 256, 256>>>();
    k_push<<<GRID, NTHREADS, smem>>>(X, out);
}

// round 5
// speedup vs baseline: 1.5135x; 1.0696x over previous
#include <cuda_runtime.h>

#define NN 2048
#define NE 32768
#define DF 2048
#define TOPK 20
#define RMAXF 1e-5f
#define ROWS 4
#define NTILES (NN / ROWS)      // 512
#define NTHREADS 512
#define GRID 148
#define LISTCAP 512
#define TCAP 8192
#define MAXIT 500

// ---------------- device scratch ----------------
__device__ int g_deg[NN], g_indeg[NN];
__device__ int g_rowptr[NN + 1], g_colptr[NN + 1];
__device__ int g_fillr[NN], g_fillc[NN];
__device__ float g_halfinv[NN];
__device__ int g_dst[NE];   // CSR out-edges (per-row sorted)
__device__ int g_src[NE];   // CSC in-edges  (per-col sorted)
__device__ int g_perm[NN];  // columns sorted by in-degree
__device__ int g_work;

// ---------------- graph build ----------------
__global__ void k_zero() {
    int t = threadIdx.x;
    for (int k = t; k < NN; k += blockDim.x) {
        g_deg[k] = 0; g_indeg[k] = 0; g_fillr[k] = 0; g_fillc[k] = 0;
    }
    if (t == 0) g_work = 0;
}

__global__ void k_count(const int* __restrict__ ei) {
    int e = blockIdx.x * blockDim.x + threadIdx.x;
    if (e >= NE) return;
    atomicAdd(&g_deg[ei[e]], 1);
    atomicAdd(&g_indeg[ei[NE + e]], 1);
}

__global__ void k_scan() {
    __shared__ int s[256];
    int t = threadIdx.x;
    for (int pass = 0; pass < 2; pass++) {
        const int* cnt = pass ? g_deg : g_indeg;
        int* ptr = pass ? g_rowptr : g_colptr;
        int base = t * 8;
        int v[8]; int sum = 0;
#pragma unroll
        for (int m = 0; m < 8; m++) { v[m] = cnt[base + m]; sum += v[m]; }
        s[t] = sum; __syncthreads();
        for (int off = 1; off < 256; off <<= 1) {
            int x = (t >= off) ? s[t - off] : 0;
            __syncthreads();
            s[t] += x;
            __syncthreads();
        }
        int excl = (t == 0) ? 0 : s[t - 1];
#pragma unroll
        for (int m = 0; m < 8; m++) { ptr[base + m] = excl; excl += v[m]; }
        if (t == 255) ptr[NN] = excl;
        __syncthreads();
    }
    int base = t * 8;
#pragma unroll
    for (int m = 0; m < 8; m++) {
        int d = g_deg[base + m];
        g_halfinv[base + m] = 0.5f / (d ? (float)d : 1.f);
    }
}

// counting sort of columns by in-degree -> equal-degree warp lanes in gather
__global__ void k_perm() {
    __shared__ int hist[64], base[64];
    int t = threadIdx.x;  // 256
    if (t < 64) hist[t] = 0;
    __syncthreads();
    for (int k = t; k < NN; k += 256) atomicAdd(&hist[min(g_indeg[k], 63)], 1);
    __syncthreads();
    if (t == 0) { int s = 0; for (int b = 0; b < 64; b++) { base[b] = s; s += hist[b]; } }
    __syncthreads();
    for (int k = t; k < NN; k += 256) {
        int pos = atomicAdd(&base[min(g_indeg[k], 63)], 1);
        g_perm[pos] = k;
    }
}

__global__ void k_fill(const int* __restrict__ ei) {
    int e = blockIdx.x * blockDim.x + threadIdx.x;
    if (e >= NE) return;
    int r = ei[e], c = ei[NE + e];
    int pr = atomicAdd(&g_fillr[r], 1);
    g_dst[g_rowptr[r] + pr] = c;
    int pc = atomicAdd(&g_fillc[c], 1);
    g_src[g_colptr[c] + pc] = r;
}

__device__ __forceinline__ void insort(int* a, int n) {
    for (int i = 1; i < n; i++) {
        int x = a[i]; int j = i - 1;
        while (j >= 0 && a[j] > x) { a[j + 1] = a[j]; j--; }
        a[j + 1] = x;
    }
}

__global__ void k_sort() {
    int id = blockIdx.x * blockDim.x + threadIdx.x;
    if (id >= 2 * NN) return;
    int* arr; int p0, p1;
    if (id < NN) { arr = g_src; p0 = g_colptr[id]; p1 = g_colptr[id + 1]; }
    else { arr = g_dst; p0 = g_rowptr[id - NN]; p1 = g_rowptr[id - NN + 1]; }
    int n = p1 - p0;
    if (n <= 1) return;
    if (n <= 160) {
        int buf[160];
        for (int i = 0; i < n; i++) buf[i] = arr[p0 + i];
        insort(buf, n);
        for (int i = 0; i < n; i++) arr[p0 + i] = buf[i];
    } else {
        insort(arr + p0, n);
    }
}

// ---------------- persistent all-in-shared push + fused topk/output ----------------
__global__ void __launch_bounds__(NTHREADS, 1)
k_push(const float* __restrict__ X, float* __restrict__ out) {
    extern __shared__ float sh[];
    float* pv = sh;                               // [8192] masked push*(0.5/deg)
    float* cur = pv + ROWS * NN;                  // [8192] residual
    float* Pp = cur + ROWS * NN;                  // [8192] P accumulator
    float* shh = Pp + ROWS * NN;                  // [2048] 0.5/deg
    int* scol = (int*)(shh + NN);                 // [2052] CSC colptr
    int* lt = scol + NN + 4;                      // [TCAP] touched entries
    int* lk = lt + TCAP;                          // [LISTCAP] frontier entries
    float* lw = (float*)(lk + LISTCAP);           // [LISTCAP] frontier weights
    unsigned* sbits = (unsigned*)(lw + LISTCAP);  // [256] dedupe bitset
    unsigned short* ssrc = (unsigned short*)(sbits + 256);   // [NE] src<<4
    unsigned short* sperm = ssrc + NE;            // [NN] degree-sorted columns
    __shared__ int s_cnt, s_lc, s_tc, s_nc, s_tile;
    __shared__ float s_redv[16];
    __shared__ int s_redi[16];
    __shared__ float s_tv[ROWS][TOPK];
    __shared__ int s_ti[ROWS][TOPK];

    float4* pv4 = (float4*)pv;
    float4* cur4 = (float4*)cur;
    float4* Pp4 = (float4*)Pp;

    const int tid = threadIdx.x;
    const int lane = tid & 31;
    const int wid = tid >> 5;

    // ---- stage tile-invariant graph data once per CTA
    for (int k = tid; k < NN; k += NTHREADS) shh[k] = g_halfinv[k];
    for (int k = tid; k <= NN; k += NTHREADS) scol[k] = g_colptr[k];
    for (int e = tid; e < NE; e += NTHREADS) ssrc[e] = (unsigned short)(g_src[e] << 4);
    for (int k = tid; k < NN; k += NTHREADS) sperm[k] = (unsigned short)g_perm[k];

    while (true) {
        __syncthreads();
        if (tid == 0) s_tile = atomicAdd(&g_work, 1);
        __syncthreads();
        const int t = s_tile;
        if (t >= NTILES) break;
        const int row0 = t * ROWS;

        // ---- init tile state
#pragma unroll
        for (int m = 0; m < NN / NTHREADS; m++) {
            int j = tid + NTHREADS * m;
            float4 z = make_float4(0.f, 0.f, 0.f, 0.f);
            Pp4[j] = z;
            int d = j - row0;
            if (d >= 0 && d < ROWS) ((float*)&z)[d] = 1.f;
            cur4[j] = z;
        }

        int mode = 0;   // 0: run phase A; 1: frontier in lk/cnt is valid
        int cnt = 0;

        for (int iter = 0; iter < MAXIT; iter++) {
            if (mode == 0) {
                if (tid == 0) { s_cnt = 0; s_lc = 0; s_tc = 0; s_nc = 0; }
                for (int w = tid; w < 256; w += NTHREADS) sbits[w] = 0;
                __syncthreads();
                // ---- phase A: mask, snapshot pv, keep in cur, accumulate P, count
                int c = 0;
#pragma unroll
                for (int m = 0; m < NN / NTHREADS; m++) {
                    int j = tid + NTHREADS * m;
                    float4 v = cur4[j];
                    float h = shh[j];
                    bool px = v.x >= RMAXF, py = v.y >= RMAXF,
                         pz = v.z >= RMAXF, pw = v.w >= RMAXF;
                    pv4[j] = make_float4(px ? v.x * h : 0.f, py ? v.y * h : 0.f,
                                         pz ? v.z * h : 0.f, pw ? v.w * h : 0.f);
                    if (px | py | pz | pw) {
                        float4 p = Pp4[j];
                        if (px) { p.x += 0.5f * v.x; v.x = 0.f; c++; }
                        if (py) { p.y += 0.5f * v.y; v.y = 0.f; c++; }
                        if (pz) { p.z += 0.5f * v.z; v.z = 0.f; c++; }
                        if (pw) { p.w += 0.5f * v.w; v.w = 0.f; c++; }
                        Pp4[j] = p;
                        cur4[j] = v;
                    }
                }
                c = __reduce_add_sync(0xffffffffu, c);
                if (lane == 0 && c) atomicAdd(&s_cnt, c);
                __syncthreads();
                cnt = s_cnt;
                if (cnt == 0) break;

                if (cnt > LISTCAP) {
                    // ---- dense path: pure-LDS CSC gather, degree-sorted lanes
                    bool any = false;
#pragma unroll
                    for (int m = 0; m < NN / NTHREADS; m++) {
                        int jr = sperm[tid + NTHREADS * m];
                        int p0 = scol[jr], p1 = scol[jr + 1];
                        float4 acc = cur4[jr];
#pragma unroll 4
                        for (int p = p0; p < p1; p++) {
                            float4 v = *(const float4*)((const char*)pv + ssrc[p]);
                            acc.x += v.x; acc.y += v.y; acc.z += v.z; acc.w += v.w;
                        }
                        cur4[jr] = acc;
                        any |= (acc.x >= RMAXF) | (acc.y >= RMAXF) |
                               (acc.z >= RMAXF) | (acc.w >= RMAXF);
                    }
                    if (!__syncthreads_or(any ? 1 : 0)) break;
                    continue;  // mode stays 0
                }
                // ---- sparse entry from phase A: build lk/lw from pv
#pragma unroll
                for (int m = 0; m < NN / NTHREADS; m++) {
                    int j = tid + NTHREADS * m;
                    float4 v = pv4[j];
#pragma unroll
                    for (int r = 0; r < 4; r++) {
                        float w = ((float*)&v)[r];
                        bool pr = w > 0.f;
                        unsigned msk = __ballot_sync(0xffffffffu, pr);
                        int base = 0;
                        if (lane == 0 && msk) base = atomicAdd(&s_lc, __popc(msk));
                        base = __shfl_sync(0xffffffffu, base, 0);
                        if (pr) {
                            int pos = base + __popc(msk & ((1u << lane) - 1));
                            lk[pos] = (j << 2) | r; lw[pos] = w;
                        }
                    }
                }
                __syncthreads();
            } else {
                // ---- list mode: process frontier directly (no scans)
                if (tid == 0) { s_tc = 0; s_nc = 0; }
                for (int w = tid; w < 256; w += NTHREADS) sbits[w] = 0;
                for (int l = tid; l < cnt; l += NTHREADS) {
                    int e = lk[l];
                    float v = cur[e];
                    Pp[e] += 0.5f * v;
                    lw[l] = v * shh[e >> 2];
                    cur[e] = 0.f;
                }
                __syncthreads();
            }

            // ---- scatter frontier via CSR, record touches
            for (int l = tid; l < cnt; l += NTHREADS) {
                int e = lk[l], k = e >> 2, r = e & 3;
                float w = lw[l];
                int p1 = g_rowptr[k + 1];
                for (int p = g_rowptr[k]; p < p1; p++) {
                    int d = (g_dst[p] << 2) | r;
                    atomicAdd(&cur[d], w);
                    int tp = atomicAdd(&s_tc, 1);
                    if (tp < TCAP) lt[tp] = d;
                }
            }
            __syncthreads();
            int tc = s_tc;
            if (tc > TCAP) { mode = 0; continue; }  // overflow: rebuild by phase A

            // ---- build next frontier from touched entries (bitset dedupe)
            for (int l = tid; l < tc; l += NTHREADS) {
                int e = lt[l];
                if (cur[e] >= RMAXF) {
                    unsigned bit = 1u << (e & 31);
                    unsigned old = atomicOr(&sbits[e >> 5], bit);
                    if (!(old & bit)) {
                        int pos = atomicAdd(&s_nc, 1);
                        if (pos < LISTCAP) lk[pos] = e;
                    }
                }
            }
            __syncthreads();
            int nc = s_nc;
            if (nc == 0) break;
            if (nc > LISTCAP) { mode = 0; }
            else { mode = 1; cnt = nc; }
        }
        __syncthreads();

        // ---- fused top-k per row (128 threads per row)
        const int rg = tid >> 7;
        const int tl = tid & 127;
        for (int q = 0; q < TOPK; q++) {
            float bv = -1.f; int bi = NN;
#pragma unroll
            for (int m = 0; m < NN / 128; m++) {
                int j = tl + 128 * m;
                float v = Pp[(j << 2) | rg];
                if (v > bv || (v == bv && j < bi)) { bv = v; bi = j; }
            }
#pragma unroll
            for (int off = 16; off; off >>= 1) {
                float ov = __shfl_down_sync(0xffffffffu, bv, off);
                int oi = __shfl_down_sync(0xffffffffu, bi, off);
                if (ov > bv || (ov == bv && oi < bi)) { bv = ov; bi = oi; }
            }
            if (lane == 0) { s_redv[wid] = bv; s_redi[wid] = bi; }
            __syncthreads();
            if (tl == 0) {
                float v0 = s_redv[4 * rg]; int i0 = s_redi[4 * rg];
#pragma unroll
                for (int w = 1; w < 4; w++) {
                    float v1 = s_redv[4 * rg + w]; int i1 = s_redi[4 * rg + w];
                    if (v1 > v0 || (v1 == v0 && i1 < i0)) { v0 = v1; i0 = i1; }
                }
                s_tv[rg][q] = v0; s_ti[rg][q] = i0;
                Pp[(i0 << 2) | rg] = -2.f;
            }
            __syncthreads();
        }

        // ---- output GEMV
        float tv[TOPK]; int ti[TOPK];
#pragma unroll
        for (int q = 0; q < TOPK; q++) {
            tv[q] = s_tv[rg][q];
            ti[q] = s_ti[rg][q] * (DF / 4);
        }
        const float4* X4 = (const float4*)X;
        float4* out4 = (float4*)out;
#pragma unroll
        for (int m = 0; m < DF / 4 / 128; m++) {
            int col = tl + 128 * m;
            float4 acc = make_float4(0.f, 0.f, 0.f, 0.f);
#pragma unroll
            for (int q = 0; q < TOPK; q++) {
                float w = tv[q];
                float4 x = __ldg(&X4[ti[q] + col]);
                acc.x += w * x.x; acc.y += w * x.y;
                acc.z += w * x.z; acc.w += w * x.w;
            }
            out4[(size_t)(row0 + rg) * (DF / 4) + col] = acc;
        }
    }
}

// ---------------- launch ----------------
extern "C" void kernel_launch(void* const* d_in, const int* in_sizes, int n_in,
                              void* d_out, int out_size) {
    const float* X;
    const int* ei;
    if (in_sizes[0] == 2 * NE) { ei = (const int*)d_in[0]; X = (const float*)d_in[1]; }
    else { X = (const float*)d_in[0]; ei = (const int*)d_in[1]; }
    float* out = (float*)d_out;

    const int smem = (3 * ROWS * NN + NN) * sizeof(float)        // pv,cur,Pp,shh
                   + (NN + 4 + TCAP + LISTCAP) * sizeof(int)     // scol,lt,lk
                   + LISTCAP * sizeof(float)                     // lw
                   + 256 * sizeof(unsigned)                      // sbits
                   + NE * sizeof(unsigned short)                 // ssrc
                   + NN * sizeof(unsigned short);                // sperm
    cudaFuncSetAttribute(k_push, cudaFuncAttributeMaxDynamicSharedMemorySize, smem);

    k_zero<<<1, 1024>>>();
    k_count<<<NE / 256, 256>>>(ei);
    k_scan<<<1, 256>>>();
    k_perm<<<1, 256>>>();
    k_fill<<<NE / 256, 256>>>(ei);
    k_sort<<<(2 * NN) / 256, 256>>>();
    k_push<<<GRID, NTHREADS, smem>>>(X, out);
}